// round 4
// baseline (speedup 1.0000x reference)
#include <cuda_runtime.h>

#define BATCH   2
#define SEQ     2048
#define DMODEL  1024
#define NHEADS  16
#define DK      64
#define MROWS   (BATCH*SEQ)      // 4096
#define QT      64               // q-tile / k-tile size in attention
#define PITCH   68               // smem pitch (floats), mult of 4, avoids bank repeats

// Scratch (allocation-free rule: __device__ globals)
__device__ float g_Qp[MROWS*DMODEL];
__device__ float g_Kp[MROWS*DMODEL];
__device__ float g_Vp[MROWS*DMODEL];
__device__ float g_ctx[MROWS*DMODEL];

// ---------------------------------------------------------------------------
// C[m][n] = sum_k A[m][k] * W[n][k] + bias[n]   (both operands K-contiguous)
// 128x128 tile, BK=8, 256 threads, 8x8 per thread.
// ---------------------------------------------------------------------------
__global__ __launch_bounds__(256) void gemm_nt_bias(
    const float* __restrict__ A, const float* __restrict__ W,
    const float* __restrict__ bias, float* __restrict__ C,
    int M, int N, int K)
{
    __shared__ float As[8][128];
    __shared__ float Ws[8][128];

    const int tid = threadIdx.x;
    const int bm = blockIdx.y * 128;
    const int bn = blockIdx.x * 128;
    const int tx = tid & 15;        // 0..15 -> n
    const int ty = tid >> 4;        // 0..15 -> m
    const int lr = tid >> 1;        // load row 0..127
    const int lc = (tid & 1) * 4;   // load col 0 or 4

    const float* Ag = A + (size_t)(bm + lr) * K + lc;
    const float* Wg = W + (size_t)(bn + lr) * K + lc;

    float acc[8][8];
#pragma unroll
    for (int i = 0; i < 8; i++)
#pragma unroll
        for (int j = 0; j < 8; j++) acc[i][j] = 0.f;

    for (int k0 = 0; k0 < K; k0 += 8) {
        float4 a4 = *(const float4*)(Ag + k0);
        float4 w4 = *(const float4*)(Wg + k0);
        As[lc + 0][lr] = a4.x; As[lc + 1][lr] = a4.y;
        As[lc + 2][lr] = a4.z; As[lc + 3][lr] = a4.w;
        Ws[lc + 0][lr] = w4.x; Ws[lc + 1][lr] = w4.y;
        Ws[lc + 2][lr] = w4.z; Ws[lc + 3][lr] = w4.w;
        __syncthreads();

#pragma unroll
        for (int kk = 0; kk < 8; kk++) {
            float4 a0 = *(const float4*)&As[kk][ty * 8];
            float4 a1 = *(const float4*)&As[kk][ty * 8 + 4];
            float4 w0 = *(const float4*)&Ws[kk][tx * 8];
            float4 w1 = *(const float4*)&Ws[kk][tx * 8 + 4];
            float ra[8] = {a0.x, a0.y, a0.z, a0.w, a1.x, a1.y, a1.z, a1.w};
            float rw[8] = {w0.x, w0.y, w0.z, w0.w, w1.x, w1.y, w1.z, w1.w};
#pragma unroll
            for (int i = 0; i < 8; i++)
#pragma unroll
                for (int j = 0; j < 8; j++)
                    acc[i][j] = fmaf(ra[i], rw[j], acc[i][j]);
        }
        __syncthreads();
    }

#pragma unroll
    for (int i = 0; i < 8; i++) {
        size_t row = (size_t)(bm + ty * 8 + i);
#pragma unroll
        for (int j = 0; j < 8; j += 4) {
            int col = bn + tx * 8 + j;
            float4 o;
            o.x = acc[i][j + 0] + bias[col + 0];
            o.y = acc[i][j + 1] + bias[col + 1];
            o.z = acc[i][j + 2] + bias[col + 2];
            o.w = acc[i][j + 3] + bias[col + 3];
            *(float4*)&C[row * N + col] = o;
        }
    }
}

// ---------------------------------------------------------------------------
// Fused attention: per CTA one (b, h, 64-row q-tile).
// Phase 1: stream k-tiles, compute scaled scores, write raw into attn gmem,
//          track online row max m / sum l.
// Phase 2: re-read raw scores, normalize in place, accumulate O = P @ V.
// Each CTA owns its q-rows fully -> no cross-CTA dependency.
// ---------------------------------------------------------------------------
__global__ __launch_bounds__(256) void attn_kernel(
    const float* __restrict__ Qp, const float* __restrict__ Kp,
    const float* __restrict__ Vp, float* __restrict__ attn,
    float* __restrict__ ctx)
{
    __shared__ float sA[QT * PITCH]; // Q^T (phase1) / V (phase2)
    __shared__ float sB[QT * PITCH]; // K^T (phase1) / P^T (phase2)

    const int b  = blockIdx.z;
    const int h  = blockIdx.y;
    const int q0 = blockIdx.x * QT;
    const int tid = threadIdx.x;
    const int tx = tid & 15, ty = tid >> 4;
    const int tx4 = tx * 4, ty4 = ty * 4;

    const float* Qbase = Qp + (size_t)b * SEQ * DMODEL + h * DK;
    const float* Kbase = Kp + (size_t)b * SEQ * DMODEL + h * DK;
    const float* Vbase = Vp + (size_t)b * SEQ * DMODEL + h * DK;
    float* attnBase = attn + ((size_t)(b * NHEADS + h)) * SEQ * SEQ;

    // Load Q tile transposed: sA[c][r]
    for (int i = tid; i < QT * 16; i += 256) {
        int r = i >> 4;
        int c4 = (i & 15) * 4;
        float4 v = *(const float4*)&Qbase[(size_t)(q0 + r) * DMODEL + c4];
        sA[(c4 + 0) * PITCH + r] = v.x;
        sA[(c4 + 1) * PITCH + r] = v.y;
        sA[(c4 + 2) * PITCH + r] = v.z;
        sA[(c4 + 3) * PITCH + r] = v.w;
    }

    float m[4], l[4];
#pragma unroll
    for (int i = 0; i < 4; i++) { m[i] = -1e30f; l[i] = 0.f; }
    __syncthreads();

    const float scale = 0.125f; // 1/sqrt(64)

    // ---------------- Phase 1 ----------------
    for (int kt = 0; kt < SEQ / QT; kt++) {
        for (int i = tid; i < QT * 16; i += 256) {
            int r = i >> 4;
            int c4 = (i & 15) * 4;
            float4 v = *(const float4*)&Kbase[(size_t)(kt * QT + r) * DMODEL + c4];
            sB[(c4 + 0) * PITCH + r] = v.x;
            sB[(c4 + 1) * PITCH + r] = v.y;
            sB[(c4 + 2) * PITCH + r] = v.z;
            sB[(c4 + 3) * PITCH + r] = v.w;
        }
        __syncthreads();

        float s[4][4];
#pragma unroll
        for (int i = 0; i < 4; i++)
#pragma unroll
            for (int j = 0; j < 4; j++) s[i][j] = 0.f;

#pragma unroll 4
        for (int kk = 0; kk < DK; kk++) {
            float4 qv = *(const float4*)&sA[kk * PITCH + ty4];
            float4 kv = *(const float4*)&sB[kk * PITCH + tx4];
            float rq[4] = {qv.x, qv.y, qv.z, qv.w};
            float rk[4] = {kv.x, kv.y, kv.z, kv.w};
#pragma unroll
            for (int i = 0; i < 4; i++)
#pragma unroll
                for (int j = 0; j < 4; j++)
                    s[i][j] = fmaf(rq[i], rk[j], s[i][j]);
        }

#pragma unroll
        for (int i = 0; i < 4; i++) {
#pragma unroll
            for (int j = 0; j < 4; j++) s[i][j] *= scale;
            // write raw scaled scores (scratch in the attn output region)
            float4 st = {s[i][0], s[i][1], s[i][2], s[i][3]};
            *(float4*)&attnBase[(size_t)(q0 + ty4 + i) * SEQ + kt * QT + tx4] = st;
            // online stats across the 16 tx lanes (half-warp butterflies)
            float tm = fmaxf(fmaxf(s[i][0], s[i][1]), fmaxf(s[i][2], s[i][3]));
#pragma unroll
            for (int off = 8; off >= 1; off >>= 1)
                tm = fmaxf(tm, __shfl_xor_sync(0xffffffffu, tm, off));
            float nm = fmaxf(m[i], tm);
            float rs = __expf(s[i][0] - nm) + __expf(s[i][1] - nm) +
                       __expf(s[i][2] - nm) + __expf(s[i][3] - nm);
#pragma unroll
            for (int off = 8; off >= 1; off >>= 1)
                rs += __shfl_xor_sync(0xffffffffu, rs, off);
            l[i] = l[i] * __expf(m[i] - nm) + rs;
            m[i] = nm;
        }
        __syncthreads();
    }

    float inv_l[4];
#pragma unroll
    for (int i = 0; i < 4; i++) inv_l[i] = 1.f / l[i];

    float o[4][4];
#pragma unroll
    for (int i = 0; i < 4; i++)
#pragma unroll
        for (int j = 0; j < 4; j++) o[i][j] = 0.f;

    // ---------------- Phase 2 ----------------
    for (int kt = 0; kt < SEQ / QT; kt++) {
        // V tile direct layout: sA[r][c]
        for (int i = tid; i < QT * 16; i += 256) {
            int r = i >> 4;
            int c4 = (i & 15) * 4;
            float4 v = *(const float4*)&Vbase[(size_t)(kt * QT + r) * DMODEL + c4];
            *(float4*)&sA[r * PITCH + c4] = v;
        }
        // re-read own raw scores, normalize, write back + P^T into sB
#pragma unroll
        for (int i = 0; i < 4; i++) {
            float4 sv = *(const float4*)&attnBase[(size_t)(q0 + ty4 + i) * SEQ + kt * QT + tx4];
            float p0 = __expf(sv.x - m[i]) * inv_l[i];
            float p1 = __expf(sv.y - m[i]) * inv_l[i];
            float p2 = __expf(sv.z - m[i]) * inv_l[i];
            float p3 = __expf(sv.w - m[i]) * inv_l[i];
            float4 pv = {p0, p1, p2, p3};
            *(float4*)&attnBase[(size_t)(q0 + ty4 + i) * SEQ + kt * QT + tx4] = pv;
            sB[(tx4 + 0) * PITCH + ty4 + i] = p0;
            sB[(tx4 + 1) * PITCH + ty4 + i] = p1;
            sB[(tx4 + 2) * PITCH + ty4 + i] = p2;
            sB[(tx4 + 3) * PITCH + ty4 + i] = p3;
        }
        __syncthreads();

#pragma unroll 4
        for (int kk = 0; kk < QT; kk++) {
            float4 pv = *(const float4*)&sB[kk * PITCH + ty4];
            float4 vv = *(const float4*)&sA[kk * PITCH + tx4];
            float rp[4] = {pv.x, pv.y, pv.z, pv.w};
            float rv[4] = {vv.x, vv.y, vv.z, vv.w};
#pragma unroll
            for (int i = 0; i < 4; i++)
#pragma unroll
                for (int j = 0; j < 4; j++)
                    o[i][j] = fmaf(rp[i], rv[j], o[i][j]);
        }
        __syncthreads();
    }

    float* ctxBase = ctx + (size_t)b * SEQ * DMODEL + h * DK;
#pragma unroll
    for (int i = 0; i < 4; i++) {
        float4 ov = {o[i][0], o[i][1], o[i][2], o[i][3]};
        *(float4*)&ctxBase[(size_t)(q0 + ty4 + i) * DMODEL + tx4] = ov;
    }
}

// ---------------------------------------------------------------------------
extern "C" void kernel_launch(void* const* d_in, const int* in_sizes, int n_in,
                              void* d_out, int out_size)
{
    const float* q  = (const float*)d_in[0];
    const float* k  = (const float*)d_in[1];
    const float* v  = (const float*)d_in[2];
    const float* wq = (const float*)d_in[3];
    const float* bq = (const float*)d_in[4];
    const float* wk = (const float*)d_in[5];
    const float* bk = (const float*)d_in[6];
    const float* wv = (const float*)d_in[7];
    const float* bv = (const float*)d_in[8];
    const float* wo = (const float*)d_in[9];
    const float* bo = (const float*)d_in[10];

    float* out  = (float*)d_out;
    float* attn = out + (size_t)MROWS * DMODEL;   // [B,H,S,S] after [B,S,D]

    float *Qp, *Kp, *Vp, *ctx;
    cudaGetSymbolAddress((void**)&Qp,  g_Qp);
    cudaGetSymbolAddress((void**)&Kp,  g_Kp);
    cudaGetSymbolAddress((void**)&Vp,  g_Vp);
    cudaGetSymbolAddress((void**)&ctx, g_ctx);

    dim3 ggrid(DMODEL / 128, MROWS / 128); // (8, 32)
    gemm_nt_bias<<<ggrid, 256>>>(q, wq, bq, Qp, MROWS, DMODEL, DMODEL);
    gemm_nt_bias<<<ggrid, 256>>>(k, wk, bk, Kp, MROWS, DMODEL, DMODEL);
    gemm_nt_bias<<<ggrid, 256>>>(v, wv, bv, Vp, MROWS, DMODEL, DMODEL);

    attn_kernel<<<dim3(SEQ / QT, NHEADS, BATCH), 256>>>(Qp, Kp, Vp, attn, ctx);

    gemm_nt_bias<<<ggrid, 256>>>(ctx, wo, bo, out, MROWS, DMODEL, DMODEL);
}